// round 17
// baseline (speedup 1.0000x reference)
#include <cuda_runtime.h>
#include <cuda_fp16.h>
#include <math.h>

#define N_MAX 100000
#define E_MAX 1600000
#define G_NUM 1024
#define SCAN_B 1024
#define NBLK_MAX 128   // ceil(100000/1024)=98

// ---------------- device scratch (no allocation allowed) -------------------
__device__ __align__(16) float  g_B0[(long long)N_MAX * 64]; // fp32 ping
__device__ __align__(16) float  g_B1[(long long)N_MAX * 64]; // fp32 pong
__device__ __align__(16) __half g_H0[(long long)N_MAX * 32]; // fp16 ping
__device__ __align__(16) __half g_H1[(long long)N_MAX * 32]; // fp16 pong
__device__ float g_dinv[N_MAX];
__device__ int   g_deg [N_MAX];        // zero at entry (static init + re-zero)
__device__ int   g_tmp [N_MAX];
__device__ int   g_off [N_MAX + 1];
__device__ int   g_bsum[NBLK_MAX];
__device__ int   g_pos [E_MAX];
__device__ int   g_csrc[E_MAX];
__device__ float g_pool[G_NUM * 64];

__device__ __forceinline__ float*  buf (int s) { return s == 0 ? g_B0 : g_B1; }
__device__ __forceinline__ __half* bufh(int s) { return s == 0 ? g_H0 : g_H1; }

__device__ __forceinline__ void acc8(float* a, uint4 v) {
    __half2* h = reinterpret_cast<__half2*>(&v);
#pragma unroll
    for (int i = 0; i < 4; i++) {
        float2 f = __half22float2(h[i]);
        a[2*i]   += f.x;
        a[2*i+1] += f.y;
    }
}

__device__ __forceinline__ uint4 pack8(const float* o) {
    uint4 v;
    __half2* h = reinterpret_cast<__half2*>(&v);
#pragma unroll
    for (int i = 0; i < 4; i++)
        h[i] = __floats2half2_rn(o[2*i], o[2*i+1]);
    return v;
}

// ---------------------------------------------------------------------------
// kA (block-split): blocks [0,tB) -> transform1 RAW (q0raw = x @ W1 -> B0 fp32)
//                   blocks [tB,..) -> edge rank pass (deg count + rank)
// ---------------------------------------------------------------------------
__global__ void kA(const float* __restrict__ x, const float* __restrict__ W1,
                   const int* __restrict__ ei, int N, int E, int tB)
{
    if ((int)blockIdx.x < tB) {
        __shared__ float sW[128 * 16];
        for (int i = threadIdx.x; i < 128 * 16; i += blockDim.x) sW[i] = W1[i];
        __syncthreads();
        int node = blockIdx.x * 256 + threadIdx.x;
        if (node >= N) return;

        const float4* row4 = reinterpret_cast<const float4*>(x) + (long long)node * 32;
        float acc[16];
#pragma unroll
        for (int j = 0; j < 16; j++) acc[j] = 0.f;
        for (int k4 = 0; k4 < 32; k4++) {
            float4 v4 = row4[k4];
            float vv[4] = {v4.x, v4.y, v4.z, v4.w};
#pragma unroll
            for (int u = 0; u < 4; u++) {
                int k = k4 * 4 + u;
#pragma unroll
                for (int j = 0; j < 16; j++)
                    acc[j] = fmaf(vv[u], sW[k * 16 + j], acc[j]);
            }
        }
        float4* out4 = reinterpret_cast<float4*>(g_B0) + (long long)node * 4;
#pragma unroll
        for (int j4 = 0; j4 < 4; j4++)
            out4[j4] = make_float4(acc[j4*4+0], acc[j4*4+1], acc[j4*4+2], acc[j4*4+3]);
    } else {
        int e = ((int)blockIdx.x - tB) * 256 + threadIdx.x;
        if (e < E) g_pos[e] = atomicAdd(&g_deg[ei[E + e]], 1);
    }
}

// ------------------------- scan --------------------------------------------
__global__ void k_scan1(int n) {
    __shared__ int s[SCAN_B];
    int t = threadIdx.x;
    int i = blockIdx.x * SCAN_B + t;
    int v = (i < n) ? g_deg[i] : 0;
    s[t] = v;
    __syncthreads();
#pragma unroll
    for (int d = 1; d < SCAN_B; d <<= 1) {
        int x = (t >= d) ? s[t - d] : 0;
        __syncthreads();
        s[t] += x;
        __syncthreads();
    }
    if (i < n) g_tmp[i] = s[t];
    if (t == SCAN_B - 1) g_bsum[blockIdx.x] = s[t];
}

__global__ void k_scan3(int n, int E, int nblk) {
    __shared__ int sb[NBLK_MAX];
    int t = threadIdx.x;
    if (t < NBLK_MAX) sb[t] = (t < nblk) ? g_bsum[t] : 0;
    __syncthreads();
#pragma unroll
    for (int d = 1; d < NBLK_MAX; d <<= 1) {
        int x = 0;
        if (t < NBLK_MAX && t >= d) x = sb[t - d];
        __syncthreads();
        if (t < NBLK_MAX) sb[t] += x;
        __syncthreads();
    }
    int i = blockIdx.x * blockDim.x + t;
    if (i < n) {
        int deg = g_deg[i];
        int blk = i / SCAN_B;
        int base = (blk == 0) ? 0 : sb[blk - 1];
        g_off[i] = g_tmp[i] - deg + base;
        g_dinv[i] = rsqrtf((float)(deg + 1));
    }
    if (i < G_NUM * 64) g_pool[i] = 0.f;
    if (i == 0) g_off[n] = E;
}

// place edges + prescale q0 (B0 fp32 -> H0 fp16, *dinv) + deg re-zero
__global__ void k_place(const int* __restrict__ ei, int E, int n) {
    int e = blockIdx.x * blockDim.x + threadIdx.x;
    if (e < n * 2) {                       // 2 uint4 (8+8 halves) per node
        int node = e >> 1;
        int part = e & 1;
        float d = g_dinv[node];
        const float4* B04 = reinterpret_cast<const float4*>(g_B0);
        float4 v0 = B04[(long long)node * 4 + part * 2 + 0];
        float4 v1 = B04[(long long)node * 4 + part * 2 + 1];
        float o[8] = {v0.x*d, v0.y*d, v0.z*d, v0.w*d,
                      v1.x*d, v1.y*d, v1.z*d, v1.w*d};
        reinterpret_cast<uint4*>(g_H0)[(long long)node * 2 + part] = pack8(o);
    }
    if (e < n) g_deg[e] = 0;
    if (e >= E) return;
    g_csrc[g_off[ei[E + e]] + g_pos[e]] = ei[e];
}

// ---------------------------------------------------------------------------
// fp16-input gather. L = uint4 lanes per row (2 -> F=16, 4 -> F=32).
// Each lane accumulates 8 features in fp32. FUSED: out = relu(m+b)*dinv (fp16).
// !FUSED: out = m (fp32).
// ---------------------------------------------------------------------------
template <int L, bool FUSED>
__global__ void k_gath(int in_sel, int out_sel,
                       const float* __restrict__ bias, int n)
{
    constexpr int SLOTS = 32 / L;
    int node = blockIdx.x * blockDim.y + threadIdx.y;
    if (node >= n) return;
    int lane = threadIdx.x;
    int slot = lane / L;
    int f4   = lane % L;

    const uint4* In = reinterpret_cast<const uint4*>(bufh(in_sel));
    int e0 = g_off[node];
    int e1 = g_off[node + 1];

    float a[8], b[8];
#pragma unroll
    for (int i = 0; i < 8; i++) { a[i] = 0.f; b[i] = 0.f; }
    if (slot == 0) acc8(a, In[(long long)node * L + f4]);   // self-loop

    int e = e0 + slot;
    for (; e + SLOTS < e1; e += 2 * SLOTS) {
        int s0 = g_csrc[e];
        int s1 = g_csrc[e + SLOTS];
        uint4 v0 = In[(long long)s0 * L + f4];
        uint4 v1 = In[(long long)s1 * L + f4];
        acc8(a, v0);
        acc8(b, v1);
    }
    if (e < e1) acc8(a, In[(long long)g_csrc[e] * L + f4]);
#pragma unroll
    for (int i = 0; i < 8; i++) a[i] += b[i];

#pragma unroll
    for (int off = 16; off >= L; off >>= 1) {
#pragma unroll
        for (int i = 0; i < 8; i++)
            a[i] += __shfl_xor_sync(0xffffffffu, a[i], off);
    }

    if (slot == 0) {
        float di = g_dinv[node];
        float o[8];
        if (FUSED) {
#pragma unroll
            for (int i = 0; i < 8; i++)
                o[i] = fmaxf(a[i] * di + bias[f4 * 8 + i], 0.f) * di;
            reinterpret_cast<uint4*>(bufh(out_sel))[(long long)node * L + f4] = pack8(o);
        } else {
#pragma unroll
            for (int i = 0; i < 8; i++) o[i] = a[i] * di;
            float4* O4 = reinterpret_cast<float4*>(buf(out_sel));
            O4[(long long)node * (2 * L) + f4 * 2 + 0] = make_float4(o[0], o[1], o[2], o[3]);
            O4[(long long)node * (2 * L) + f4 * 2 + 1] = make_float4(o[4], o[5], o[6], o[7]);
        }
    }
}

// ---------------------------------------------------------------------------
// Node transform: acc = in(fp32) @ W; OUT_HALF: relu(+b)*dinv -> fp16
//                                     else:     relu(+b)      -> fp32
// ---------------------------------------------------------------------------
template <int F_IN, int F_OUT, bool OUT_HALF>
__global__ void k_transform(int in_sel, int out_sel,
                            const float* __restrict__ W,
                            const float* __restrict__ bout, int n)
{
    __shared__ float sW[F_IN * F_OUT];
    for (int i = threadIdx.x; i < F_IN * F_OUT; i += blockDim.x) sW[i] = W[i];
    __syncthreads();

    int node = blockIdx.x * blockDim.x + threadIdx.x;
    if (node >= n) return;

    const float4* row4 = reinterpret_cast<const float4*>(buf(in_sel)) +
                         (long long)node * (F_IN / 4);

    float acc[F_OUT];
#pragma unroll
    for (int j = 0; j < F_OUT; j++) acc[j] = 0.f;

    for (int k4 = 0; k4 < F_IN / 4; k4++) {
        float4 v4 = row4[k4];
        float vv[4] = {v4.x, v4.y, v4.z, v4.w};
#pragma unroll
        for (int u = 0; u < 4; u++) {
            int k = k4 * 4 + u;
#pragma unroll
            for (int j = 0; j < F_OUT; j++)
                acc[j] = fmaf(vv[u], sW[k * F_OUT + j], acc[j]);
        }
    }

    float di = g_dinv[node];
    if (OUT_HALF) {
        uint4* outh = reinterpret_cast<uint4*>(bufh(out_sel)) +
                      (long long)node * (F_OUT / 8);
#pragma unroll
        for (int j8 = 0; j8 < F_OUT / 8; j8++) {
            float o[8];
#pragma unroll
            for (int u = 0; u < 8; u++)
                o[u] = fmaxf(acc[j8 * 8 + u] + bout[j8 * 8 + u], 0.f) * di;
            outh[j8] = pack8(o);
        }
    } else {
        float4* out4 = reinterpret_cast<float4*>(buf(out_sel)) +
                       (long long)node * (F_OUT / 4);
#pragma unroll
        for (int j4 = 0; j4 < F_OUT / 4; j4++) {
            float o[4];
#pragma unroll
            for (int u = 0; u < 4; u++)
                o[u] = fmaxf(acc[j4 * 4 + u] + bout[j4 * 4 + u], 0.f);
            out4[j4] = make_float4(o[0], o[1], o[2], o[3]);
        }
    }
}

// ----------------- pool: segment max over sorted batch ids -----------------
__global__ void k_pool(int in_sel, const int* __restrict__ batch, int n)
{
    int f = threadIdx.x;
    int chunk = blockIdx.x * blockDim.y + threadIdx.y;
    int n0 = chunk * 16;
    if (n0 >= n) return;
    int n1 = min(n0 + 16, n);
    const float* h = buf(in_sel);

    int curg = batch[n0];
    float m = h[(long long)n0 * 64 + f];
    for (int i = n0 + 1; i < n1; i++) {
        int g = batch[i];
        float v = h[(long long)i * 64 + f];
        if (g != curg) {
            atomicMax((unsigned int*)&g_pool[curg * 64 + f], __float_as_uint(m));
            curg = g;
            m = v;
        } else {
            m = fmaxf(m, v);
        }
    }
    atomicMax((unsigned int*)&g_pool[curg * 64 + f], __float_as_uint(m));
}

// ---------------- fused MLP head (block per graph) --------------------------
__global__ void k_mlp(const float* __restrict__ W1, const float* __restrict__ b1,
                      const float* __restrict__ W2, const float* __restrict__ b2,
                      float* __restrict__ out)
{
    __shared__ float sp[64];
    __shared__ float sz[256];
    int g = blockIdx.x, j = threadIdx.x;
    if (j < 64) sp[j] = g_pool[g * 64 + j];
    __syncthreads();
    float acc = b1[j];
#pragma unroll
    for (int k = 0; k < 64; k++) acc = fmaf(sp[k], W1[k * 256 + j], acc);
    sz[j] = fmaxf(acc, 0.f);
    __syncthreads();
    float acc2 = b2[j];
#pragma unroll 8
    for (int k = 0; k < 256; k++) acc2 = fmaf(sz[k], W2[k * 256 + j], acc2);
    out[g * 256 + j] = 1.f / (1.f + expf(-acc2));
}

// ------------------------------ launch -------------------------------------
extern "C" void kernel_launch(void* const* d_in, const int* in_sizes, int n_in,
                              void* d_out, int out_size)
{
    const float* x     = (const float*)d_in[0];
    const int*   ei    = (const int*)d_in[1];    // int32 (JAX x64 disabled)
    const int*   batch = (const int*)d_in[2];
    const float* W1 = (const float*)d_in[3];
    const float* b1 = (const float*)d_in[4];
    const float* W2 = (const float*)d_in[5];
    const float* b2 = (const float*)d_in[6];
    const float* W3 = (const float*)d_in[7];
    const float* b3 = (const float*)d_in[8];
    const float* L1w = (const float*)d_in[9];
    const float* L1b = (const float*)d_in[10];
    const float* L2w = (const float*)d_in[11];
    const float* L2b = (const float*)d_in[12];
    float* out = (float*)d_out;

    int N = in_sizes[0] / 128;
    int E = in_sizes[1] / 2;
    int nblk = (N + SCAN_B - 1) / SCAN_B;
    int tB   = (N + 255) / 256;
    int pB   = (E + 255) / 256;

    // transform1 (raw fp32) overlapped with edge-rank pass
    kA      <<<tB + pB, 256>>>(x, W1, ei, N, E, tB);
    k_scan1 <<<nblk, SCAN_B>>>(N);
    k_scan3 <<<(N + 255) / 256, 256>>>(N, E, nblk);
    // place + prescale q0 -> H0 fp16 + deg re-zero
    { int m = (E > 2 * N) ? E : 2 * N;
      k_place <<<(m + 255) / 256, 256>>>(ei, E, N); }

    dim3 gb(32, 8);
    int ggrid = (N + 7) / 8;

    // q1 = relu(dinv*(q0+Σq0) + b1)*dinv   H0 -> H1 (fp16), F=16
    k_gath<2, true ><<<ggrid, gb>>>(0, 1, b1, N);
    // m2 = dinv*(q1+Σq1)                   H1 -> B0 (fp32), F=16
    k_gath<2, false><<<ggrid, gb>>>(1, 0, nullptr, N);
    // q2 = relu(m2@W2 + b2)*dinv           B0 -> H0 (fp16), F=32
    k_transform<16, 32, true ><<<(N + 127) / 128, 128>>>(0, 0, W2, b2, N);
    // m3 = dinv*(q2+Σq2)                   H0 -> B1 (fp32), F=32
    k_gath<4, false><<<ggrid, gb>>>(0, 1, nullptr, N);
    // h3 = relu(m3@W3 + b3)                B1 -> B0 (fp32), F=64
    k_transform<32, 64, false><<<(N + 127) / 128, 128>>>(1, 0, W3, b3, N);

    { dim3 pb(64, 4); int chunks = (N + 15) / 16;
      k_pool<<<(chunks + 3) / 4, pb>>>(0, batch, N); }
    k_mlp<<<G_NUM, 256>>>(L1w, L1b, L2w, L2b, out);
}